// round 15
// baseline (speedup 1.0000x reference)
#include <cuda_runtime.h>
#include <cuda_fp16.h>
#include <math.h>
#include <stdint.h>

#define BB 2
#define TT 2048
#define DD 1024
#define HH 16
#define HD 64
#define MM (BB*TT)

// Scratch (device globals: no allocations allowed)
__device__ __half g_xh [(size_t)MM * DD];      // rounded x (half)
__device__ __half g_qk [(size_t)MM * 2 * DD];  // q|k projections (half)
__device__ float  g_yar[(size_t)MM * DD];      // y_ar fp32
__device__ __half g_ym [(size_t)MM * DD];      // rnd(y_ar + y_ma) half
__device__ __half g_ka [(size_t)MM * DD];      // sigmoid(k2*.0025) half (row T-1 don't-care)
__device__ __half g_e  [(size_t)MM * DD];      // x[t+1]-yar[t] half, row T-1 = 0
__device__ __half g_wa [(size_t)2*DD*DD];      // w_attn half
__device__ __half g_wk [(size_t)DD*DD];        // w_k2 half
__device__ __half g_wp [(size_t)DD*DD];        // w_proj half

// ---------------------------------------------------------------------------
__device__ __forceinline__ uint32_t h2u(__half2 h) { return *(uint32_t*)&h; }
__device__ __forceinline__ uint32_t packf(float a, float b) {
    __half2 h = __floats2half2_rn(a, b); return h2u(h);
}
__device__ __forceinline__ void mma16(float* d, const uint32_t* a, const uint32_t* b) {
    asm("mma.sync.aligned.m16n8k16.row.col.f32.f16.f16.f32 "
        "{%0,%1,%2,%3},{%4,%5,%6,%7},{%8,%9},{%0,%1,%2,%3};"
        : "+f"(d[0]), "+f"(d[1]), "+f"(d[2]), "+f"(d[3])
        : "r"(a[0]), "r"(a[1]), "r"(a[2]), "r"(a[3]), "r"(b[0]), "r"(b[1]));
}
__device__ __forceinline__ void ldsm4(uint32_t* r, uint32_t addr) {
    asm volatile("ldmatrix.sync.aligned.m8n8.x4.shared.b16 {%0,%1,%2,%3}, [%4];"
        : "=r"(r[0]), "=r"(r[1]), "=r"(r[2]), "=r"(r[3]) : "r"(addr));
}
__device__ __forceinline__ void ldsm4t(uint32_t* r, uint32_t addr) {
    asm volatile("ldmatrix.sync.aligned.m8n8.x4.trans.shared.b16 {%0,%1,%2,%3}, [%4];"
        : "=r"(r[0]), "=r"(r[1]), "=r"(r[2]), "=r"(r[3]) : "r"(addr));
}
__device__ __forceinline__ void cpa16(void* dst, const void* src) {
    uint32_t d = (uint32_t)__cvta_generic_to_shared(dst);
    asm volatile("cp.async.cg.shared.global [%0], [%1], 16;" :: "r"(d), "l"(src));
}
__device__ __forceinline__ uint32_t ex2h2(uint32_t t) {
    uint32_t r;
    asm("ex2.approx.f16x2 %0, %1;" : "=r"(r) : "r"(t));
    return r;
}
#define CP_COMMIT asm volatile("cp.async.commit_group;" ::: "memory")
#define CP_WAIT1  asm volatile("cp.async.wait_group 1;" ::: "memory")
#define CP_WAIT0  asm volatile("cp.async.wait_group 0;" ::: "memory")

// ---------------------------------------------------------------------------
// Elementwise f32 -> f16 rounding; each thread handles 8 floats.
// ---------------------------------------------------------------------------
__global__ void __launch_bounds__(256) round_h_kernel(
    const float* __restrict__ in, __half* __restrict__ out, int n8)
{
    int i = blockIdx.x * 256 + threadIdx.x;
    if (i < n8) {
        float4 a = ((const float4*)in)[2*i], b = ((const float4*)in)[2*i+1];
        uint4 r = make_uint4(packf(a.x, a.y), packf(a.z, a.w),
                             packf(b.x, b.y), packf(b.z, b.w));
        ((uint4*)out)[i] = r;
    }
}

// ---------------------------------------------------------------------------
// GEMM (R12-proven): C = A*W^T + bscale*bias. 128x128 tile, 8 warps (2m x 4n),
// Kc=32, 3-stage cp.async, one sync per iter.
// out_mode: 0 = f32, 1 = f16, 2 = f16 sigmoid(v*0.0025)  (ka path)
// ---------------------------------------------------------------------------
#define GST 40
#define GSTAGE (2 * 128 * GST)                 // halves per stage (A+W)
#define GEMM_SMEM (3 * GSTAGE * 2)             // 61440 B
__global__ void __launch_bounds__(256, 2) gemm_tc(
    const __half* __restrict__ A, const __half* __restrict__ W,
    const float* __restrict__ bias, float bscale,
    void* __restrict__ Cout, int out_mode, int N, int K)
{
    extern __shared__ __half gsm[];
    const int tid = threadIdx.x;
    const int wid = tid >> 5, lane = tid & 31;
    const int g = lane >> 2, c = lane & 3;
    const int r8 = lane & 7, sel = lane >> 3;
    const int m0 = blockIdx.y << 7, n0 = blockIdx.x << 7;
    const int wm = (wid >> 2) << 6;
    const int wn = (wid & 3) << 5;

    const int nit = K >> 5;
    float acc[4][4][4] = {};

    auto issue = [&](int it, int st) {
        __half* As = gsm + st * GSTAGE;
        __half* Ws = As + 128 * GST;
        const int k0 = it << 5;
#pragma unroll
        for (int l = 0; l < 4; l++) {
            int id = tid + l * 256;
            int arr = id >> 9, idr = id & 511;
            int r = idr >> 2, ch = (idr & 3) << 3;
            if (!arr) cpa16(&As[r * GST + ch], A + (size_t)(m0 + r) * K + k0 + ch);
            else      cpa16(&Ws[r * GST + ch], W + (size_t)(n0 + r) * K + k0 + ch);
        }
        CP_COMMIT;
    };

    issue(0, 0);
    issue(1, 1);
    for (int it = 0; it < nit; it++) {
        const int cur = it % 3;
        if (it + 1 < nit) { CP_WAIT1; } else { CP_WAIT0; }
        __syncthreads();
        if (it + 2 < nit) issue(it + 2, (it + 2) % 3);
        const __half* As = gsm + cur * GSTAGE;
        const __half* Ws = As + 128 * GST;
#pragma unroll
        for (int kk = 0; kk < 32; kk += 16) {
            uint32_t a[4][4], b[4][2];
#pragma unroll
            for (int mt = 0; mt < 4; mt++) {
                const int row = wm + mt * 16 + r8 + ((sel & 1) << 3);
                const int col = kk + ((sel >> 1) << 3);
                ldsm4(a[mt], (uint32_t)__cvta_generic_to_shared(&As[row * GST + col]));
            }
#pragma unroll
            for (int np = 0; np < 2; np++) {
                const int row = wn + ((2 * np + (sel >> 1)) << 3) + r8;
                const int col = kk + ((sel & 1) << 3);
                uint32_t t4[4];
                ldsm4(t4, (uint32_t)__cvta_generic_to_shared(&Ws[row * GST + col]));
                b[2*np][0] = t4[0]; b[2*np][1] = t4[1];
                b[2*np+1][0] = t4[2]; b[2*np+1][1] = t4[3];
            }
#pragma unroll
            for (int mt = 0; mt < 4; mt++)
#pragma unroll
                for (int nt = 0; nt < 4; nt++)
                    mma16(acc[mt][nt], a[mt], b[nt]);
        }
    }
#pragma unroll
    for (int mt = 0; mt < 4; mt++) {
#pragma unroll
        for (int nt = 0; nt < 4; nt++) {
            const int col = n0 + wn + nt * 8 + 2 * c;
            const float b0 = bscale * bias[col], b1 = bscale * bias[col + 1];
            const int row = m0 + wm + mt * 16 + g;
            float v0 = acc[mt][nt][0] + b0, v1 = acc[mt][nt][1] + b1;
            float v2 = acc[mt][nt][2] + b0, v3 = acc[mt][nt][3] + b1;
            if (out_mode == 0) {
                float* Cf = (float*)Cout;
                *(float2*)(Cf + (size_t)row * N + col) = make_float2(v0, v1);
                *(float2*)(Cf + (size_t)(row + 8) * N + col) = make_float2(v2, v3);
            } else {
                if (out_mode == 2) {
                    v0 = 1.f / (1.f + __expf(-v0 * 0.0025f));
                    v1 = 1.f / (1.f + __expf(-v1 * 0.0025f));
                    v2 = 1.f / (1.f + __expf(-v2 * 0.0025f));
                    v3 = 1.f / (1.f + __expf(-v3 * 0.0025f));
                }
                __half* Ch = (__half*)Cout;
                *(uint32_t*)(Ch + (size_t)row * N + col) = packf(v0, v1);
                *(uint32_t*)(Ch + (size_t)(row + 8) * N + col) = packf(v2, v3);
            }
        }
    }
}

// ---------------------------------------------------------------------------
// Flash kernels v2: Q 128 x KV 64, 8 warps in a 4q x 2kv SPLIT:
// each warp owns 32 q-rows x 32 kv-cols -> K/V LDSM traffic per warp HALVES
// vs the 16-row layout (each K/V fragment reused across 2x the q rows).
// kv halves are combined once at the end via a smem reduction (kvh=1 warps
// store partial O/li; kvh=0 warps add + write). Static-shift softmax
// (p=exp(s-3), ex2.f16x2 fused into the P pack; li via ones-mma).
// occupancy 1 (reg pressure from 32-row accumulators).
// ---------------------------------------------------------------------------
#define QST 72
#define KST 72
#define OFF_K (128*QST)              // halves
#define FST   (2*64*KST)             // K+V halves per stage
#define FLASH_SMEM ((128*QST + 3*FST) * 2)   // 73728 B
#define FAS 66                        // f32 reduce buffer stride

__global__ void __launch_bounds__(256, 1) flash_ar_tc(
    const __half* __restrict__ qk, const __half* __restrict__ xh,
    const float* __restrict__ xf,
    float* __restrict__ yar, __half* __restrict__ eout)
{
    extern __shared__ __half fsm[];
    __half* Qs = fsm;

    const int qt = (gridDim.x - 1) - blockIdx.x;   // heavy tiles first
    const int b = blockIdx.y >> 4, h = blockIdx.y & 15;
    const int tid = threadIdx.x, wid = tid >> 5, lane = tid & 31;
    const int g = lane >> 2, c = lane & 3;
    const int r8 = lane & 7, sel = lane >> 3;
    const int q0 = qt << 7;
    const int qg = wid >> 1, kvh = wid & 1;
    const int qbr = qg << 5;          // warp q-row base (0/32/64/96)
    const int kvc = kvh << 5;         // warp kv-col base (0/32)

    const __half* qbase = qk + (size_t)b * TT * (2 * DD) + h * HD;
    const __half* kbase = qbase + DD;
    const __half* vbase = xh + (size_t)b * TT * DD + h * HD;

    auto issue = [&](int kt, int st) {
        __half* Ksm = fsm + OFF_K + st * FST;
        __half* Vsm = Ksm + 64 * KST;
        const int k0 = kt << 6;
#pragma unroll
        for (int l = 0; l < 4; l++) {
            int id = tid + l * 256;
            int arr = id >> 9, idr = id & 511;
            int r = idr >> 3, ch = (idr & 7) << 3;
            if (!arr) cpa16(&Ksm[r * KST + ch], kbase + (size_t)(k0 + r) * (2 * DD) + ch);
            else      cpa16(&Vsm[r * KST + ch], vbase + (size_t)(k0 + r) * DD + ch);
        }
        CP_COMMIT;
    };

    const int nkt = 2 * qt + 2;
    // Q fill: scale by 0.125 (exact in half)
    {
        const __half2 sc = __float2half2_rn(0.125f);
#pragma unroll
        for (int l = 0; l < 4; l++) {
            int id = tid + l * 256;
            int r = id >> 3, ch = (id & 7) << 3;
            uint4 v = *(const uint4*)(qbase + (size_t)(q0 + r) * (2 * DD) + ch);
            __half2* p = (__half2*)&v;
            p[0] = __hmul2(p[0], sc); p[1] = __hmul2(p[1], sc);
            p[2] = __hmul2(p[2], sc); p[3] = __hmul2(p[3], sc);
            *(uint4*)&Qs[r * QST + ch] = v;
        }
    }
    issue(0, 0);
    if (nkt > 1) issue(1, 1);
    __syncthreads();

    // Preload Q fragments: 2 m16 tiles x 4 k16 chunks
    uint32_t aq[2][4][4];
#pragma unroll
    for (int mt = 0; mt < 2; mt++)
#pragma unroll
        for (int ks = 0; ks < 4; ks++) {
            const int row = qbr + mt * 16 + r8 + ((sel & 1) << 3);
            const int col = ks * 16 + ((sel >> 1) << 3);
            ldsm4(aq[mt][ks], (uint32_t)__cvta_generic_to_shared(&Qs[row * QST + col]));
        }

    const uint32_t ones[2] = {0x3C003C00u, 0x3C003C00u};
    float accli[2][4] = {};
    float acc[2][8][4] = {};

    for (int kt = 0; kt < nkt; kt++) {
        const int cur = kt % 3;
        const int k0 = kt << 6;
        if (kt + 1 < nkt) { CP_WAIT1; } else { CP_WAIT0; }
        __syncthreads();
        if (kt + 2 < nkt) issue(kt + 2, (kt + 2) % 3);
        const __half* Ksm = fsm + OFF_K + cur * FST;
        const __half* Vsm = Ksm + 64 * KST;

        float s[2][4][4] = {};
#pragma unroll
        for (int ks = 0; ks < 4; ks++) {
            uint32_t bk[4][2];
#pragma unroll
            for (int np = 0; np < 2; np++) {
                const int row = kvc + ((2 * np + (sel >> 1)) << 3) + r8;
                const int col = ks * 16 + ((sel & 1) << 3);
                uint32_t t4[4];
                ldsm4(t4, (uint32_t)__cvta_generic_to_shared(&Ksm[row * KST + col]));
                bk[2*np][0] = t4[0]; bk[2*np][1] = t4[1];
                bk[2*np+1][0] = t4[2]; bk[2*np+1][1] = t4[3];
            }
#pragma unroll
            for (int mt = 0; mt < 2; mt++)
#pragma unroll
                for (int nt = 0; nt < 4; nt++)
                    mma16(s[mt][nt], aq[mt][ks], bk[nt]);
        }
        if (kt >= 2 * qt) {
#pragma unroll
            for (int mt = 0; mt < 2; mt++) {
                const int rr0 = q0 + qbr + mt * 16 + g, rr1 = rr0 + 8;
#pragma unroll
                for (int nt = 0; nt < 4; nt++) {
                    const int col = k0 + kvc + nt * 8 + 2 * c;
                    if (col     > rr0) s[mt][nt][0] = -INFINITY;
                    if (col + 1 > rr0) s[mt][nt][1] = -INFINITY;
                    if (col     > rr1) s[mt][nt][2] = -INFINITY;
                    if (col + 1 > rr1) s[mt][nt][3] = -INFINITY;
                }
            }
        }
        // p = 2^(s*log2e - 3*log2e), fused exp + A-frag pack
        const float L2E = 1.44269504f, C3 = 4.32808512f;
        uint32_t ap[2][2][4];
#pragma unroll
        for (int mt = 0; mt < 2; mt++)
#pragma unroll
            for (int kb = 0; kb < 2; kb++)
#pragma unroll
                for (int r = 0; r < 4; r++) {
                    const int nt = 2 * kb + (r >> 1);
                    const int j0 = (r & 1) << 1;
                    ap[mt][kb][r] = ex2h2(packf(fmaf(s[mt][nt][j0],     L2E, -C3),
                                                fmaf(s[mt][nt][j0 + 1], L2E, -C3)));
                }
#pragma unroll
        for (int kb = 0; kb < 2; kb++) {
            uint32_t bv[8][2];
#pragma unroll
            for (int np = 0; np < 4; np++) {
                const int row = kvc + kb * 16 + ((sel & 1) << 3) + r8;
                const int col = ((2 * np + (sel >> 1)) << 3);
                uint32_t t4[4];
                ldsm4t(t4, (uint32_t)__cvta_generic_to_shared(&Vsm[row * KST + col]));
                bv[2*np][0] = t4[0]; bv[2*np][1] = t4[1];
                bv[2*np+1][0] = t4[2]; bv[2*np+1][1] = t4[3];
            }
#pragma unroll
            for (int mt = 0; mt < 2; mt++) {
#pragma unroll
                for (int nt = 0; nt < 8; nt++)
                    mma16(acc[mt][nt], ap[mt][kb], bv[nt]);
                mma16(accli[mt], ap[mt][kb], ones);
            }
        }
    }
    // cross-warp kv reduction + epilogue
    __syncthreads();
    float* Facc = (float*)fsm;               // [128][FAS]
    float* Fli  = (float*)fsm + 128 * FAS;   // [128]
    if (kvh == 1) {
#pragma unroll
        for (int mt = 0; mt < 2; mt++) {
            const int r0 = qbr + mt * 16 + g;
#pragma unroll
            for (int nt = 0; nt < 8; nt++) {
                const int col = nt * 8 + 2 * c;
                *(float2*)&Facc[r0 * FAS + col] = make_float2(acc[mt][nt][0], acc[mt][nt][1]);
                *(float2*)&Facc[(r0 + 8) * FAS + col] = make_float2(acc[mt][nt][2], acc[mt][nt][3]);
            }
            if (c == 0) { Fli[r0] = accli[mt][0]; Fli[r0 + 8] = accli[mt][2]; }
        }
    }
    __syncthreads();
    if (kvh == 0) {
#pragma unroll
        for (int mt = 0; mt < 2; mt++) {
            const int r0 = qbr + mt * 16 + g;
            const float inv[2] = {1.f / (accli[mt][0] + Fli[r0]),
                                  1.f / (accli[mt][2] + Fli[r0 + 8])};
#pragma unroll
            for (int half = 0; half < 2; half++) {
                const int rl = r0 + half * 8;
                const int t = q0 + rl;
                float* opy = yar + ((size_t)b * TT + t) * DD + h * HD;
                __half* ope = eout + ((size_t)b * TT + t) * DD + h * HD;
                const float* xr = xf + ((size_t)b * TT + t + 1) * DD + h * HD;
                const bool has_e = (t < TT - 1);
#pragma unroll
                for (int nt = 0; nt < 8; nt++) {
                    const int col = nt * 8 + 2 * c;
                    const float y0 = (acc[mt][nt][2*half]   + Facc[rl * FAS + col])     * inv[half];
                    const float y1 = (acc[mt][nt][2*half+1] + Facc[rl * FAS + col + 1]) * inv[half];
                    *(float2*)(opy + col) = make_float2(y0, y1);
                    if (has_e) {
                        float2 xv = *(const float2*)(xr + col);
                        *(uint32_t*)(ope + col) = packf(xv.x - y0, xv.y - y1);
                    } else {
                        *(uint32_t*)(ope + col) = 0u;
                    }
                }
            }
        }
    }
}

// ---------------------------------------------------------------------------
// ARMA branch v2 (same 4q x 2kv split). Output half = rnd(y_ma + y_ar).
// ---------------------------------------------------------------------------
__global__ void __launch_bounds__(256, 1) flash_ma_tc(
    const __half* __restrict__ qk, const __half* __restrict__ ka,
    const __half* __restrict__ ev, const float* __restrict__ yar,
    __half* __restrict__ ym)
{
    extern __shared__ __half fsm[];
    __half* Qs = fsm;

    const int qt = (gridDim.x - 1) - blockIdx.x;
    const int b = blockIdx.y >> 4, h = blockIdx.y & 15;
    const int tid = threadIdx.x, wid = tid >> 5, lane = tid & 31;
    const int g = lane >> 2, c = lane & 3;
    const int r8 = lane & 7, sel = lane >> 3;
    const int q0 = qt << 7;
    const int qg = wid >> 1, kvh = wid & 1;
    const int qbr = qg << 5;
    const int kvc = kvh << 5;
    const int Tm = TT - 1;

    const __half* qbase = qk + (size_t)b * TT * (2 * DD) + h * HD;
    const __half* kbase = ka + (size_t)b * TT * DD + h * HD;
    const __half* vbase = ev + (size_t)b * TT * DD + h * HD;

    if (qt == 0 && tid < HD)   // row 0: y_ma = 0 -> store h(yar[0])
        ym[(size_t)b * TT * DD + h * HD + tid] =
            __float2half(yar[(size_t)b * TT * DD + h * HD + tid]);

    auto issue = [&](int kt, int st) {
        __half* Ksm = fsm + OFF_K + st * FST;
        __half* Vsm = Ksm + 64 * KST;
        const int k0 = kt << 6;
#pragma unroll
        for (int l = 0; l < 4; l++) {
            int id = tid + l * 256;
            int arr = id >> 9, idr = id & 511;
            int r = idr >> 3, ch = (idr & 7) << 3;
            if (!arr) cpa16(&Ksm[r * KST + ch], kbase + (size_t)(k0 + r) * DD + ch);
            else      cpa16(&Vsm[r * KST + ch], vbase + (size_t)(k0 + r) * DD + ch);
        }
        CP_COMMIT;
    };

    const int nkt = 2 * qt + 2;
    // Q fill: qa = h(min(u, 0.02u)), u = q*0.125
#pragma unroll
    for (int l = 0; l < 4; l++) {
        int id = tid + l * 256;
        int r = id >> 3, ch = (id & 7) << 3;
        int t = q0 + r;
        uint4 o = make_uint4(0u, 0u, 0u, 0u);
        if (t < Tm) {
            uint4 v = *(const uint4*)(qbase + (size_t)(t + 1) * (2 * DD) + ch);
            const __half2* p = (const __half2*)&v;
            uint32_t* q = (uint32_t*)&o;
#pragma unroll
            for (int j = 0; j < 4; j++) {
                float2 f = __half22float2(p[j]);
                f.x *= 0.125f; f.y *= 0.125f;
                q[j] = packf(fminf(f.x, 0.02f * f.x), fminf(f.y, 0.02f * f.y));
            }
        }
        *(uint4*)&Qs[r * QST + ch] = o;
    }
    issue(0, 0);
    if (nkt > 1) issue(1, 1);
    __syncthreads();

    uint32_t aq[2][4][4];
#pragma unroll
    for (int mt = 0; mt < 2; mt++)
#pragma unroll
        for (int ks = 0; ks < 4; ks++) {
            const int row = qbr + mt * 16 + r8 + ((sel & 1) << 3);
            const int col = ks * 16 + ((sel >> 1) << 3);
            ldsm4(aq[mt][ks], (uint32_t)__cvta_generic_to_shared(&Qs[row * QST + col]));
        }

    float acc[2][8][4] = {};
    for (int kt = 0; kt < nkt; kt++) {
        const int cur = kt % 3;
        const int k0 = kt << 6;
        if (kt + 1 < nkt) { CP_WAIT1; } else { CP_WAIT0; }
        __syncthreads();
        if (kt + 2 < nkt) issue(kt + 2, (kt + 2) % 3);
        const __half* Ksm = fsm + OFF_K + cur * FST;
        const __half* Vsm = Ksm + 64 * KST;

        float s[2][4][4] = {};
#pragma unroll
        for (int ks = 0; ks < 4; ks++) {
            uint32_t bk[4][2];
#pragma unroll
            for (int np = 0; np < 2; np++) {
                const int row = kvc + ((2 * np + (sel >> 1)) << 3) + r8;
                const int col = ks * 16 + ((sel & 1) << 3);
                uint32_t t4[4];
                ldsm4(t4, (uint32_t)__cvta_generic_to_shared(&Ksm[row * KST + col]));
                bk[2*np][0] = t4[0]; bk[2*np][1] = t4[1];
                bk[2*np+1][0] = t4[2]; bk[2*np+1][1] = t4[3];
            }
#pragma unroll
            for (int mt = 0; mt < 2; mt++)
#pragma unroll
                for (int nt = 0; nt < 4; nt++)
                    mma16(s[mt][nt], aq[mt][ks], bk[nt]);
        }
        if (kt >= 2 * qt) {
#pragma unroll
            for (int mt = 0; mt < 2; mt++) {
                const int rr0 = q0 + qbr + mt * 16 + g, rr1 = rr0 + 8;
#pragma unroll
                for (int nt = 0; nt < 4; nt++) {
                    const int col = k0 + kvc + nt * 8 + 2 * c;
                    if (col     > rr0) s[mt][nt][0] = 0.f;
                    if (col + 1 > rr0) s[mt][nt][1] = 0.f;
                    if (col     > rr1) s[mt][nt][2] = 0.f;
                    if (col + 1 > rr1) s[mt][nt][3] = 0.f;
                }
            }
        }
        uint32_t ap[2][2][4];
#pragma unroll
        for (int mt = 0; mt < 2; mt++)
#pragma unroll
            for (int kb = 0; kb < 2; kb++) {
                ap[mt][kb][0] = packf(s[mt][2*kb][0],   s[mt][2*kb][1]);
                ap[mt][kb][1] = packf(s[mt][2*kb][2],   s[mt][2*kb][3]);
                ap[mt][kb][2] = packf(s[mt][2*kb+1][0], s[mt][2*kb+1][1]);
                ap[mt][kb][3] = packf(s[mt][2*kb+1][2], s[mt][2*kb+1][3]);
            }
#pragma unroll
        for (int kb = 0; kb < 2; kb++) {
            uint32_t bv[8][2];
#pragma unroll
            for (int np = 0; np < 4; np++) {
                const int row = kvc + kb * 16 + ((sel & 1) << 3) + r8;
                const int col = ((2 * np + (sel >> 1)) << 3);
                uint32_t t4[4];
                ldsm4t(t4, (uint32_t)__cvta_generic_to_shared(&Vsm[row * KST + col]));
                bv[2*np][0] = t4[0]; bv[2*np][1] = t4[1];
                bv[2*np+1][0] = t4[2]; bv[2*np+1][1] = t4[3];
            }
#pragma unroll
            for (int mt = 0; mt < 2; mt++)
#pragma unroll
                for (int nt = 0; nt < 8; nt++)
                    mma16(acc[mt][nt], ap[mt][kb], bv[nt]);
        }
    }
    // cross-warp kv reduction + epilogue
    __syncthreads();
    float* Facc = (float*)fsm;
    if (kvh == 1) {
#pragma unroll
        for (int mt = 0; mt < 2; mt++) {
            const int r0 = qbr + mt * 16 + g;
#pragma unroll
            for (int nt = 0; nt < 8; nt++) {
                const int col = nt * 8 + 2 * c;
                *(float2*)&Facc[r0 * FAS + col] = make_float2(acc[mt][nt][0], acc[mt][nt][1]);
                *(float2*)&Facc[(r0 + 8) * FAS + col] = make_float2(acc[mt][nt][2], acc[mt][nt][3]);
            }
        }
    }
    __syncthreads();
    if (kvh == 0) {
#pragma unroll
        for (int mt = 0; mt < 2; mt++) {
            const int r0 = qbr + mt * 16 + g;
#pragma unroll
            for (int half = 0; half < 2; half++) {
                const int rl = r0 + half * 8;
                const int t = q0 + rl;
                if (t < Tm) {
                    const int row = t + 1;
                    const float* yr = yar + ((size_t)b * TT + row) * DD + h * HD;
                    __half* op = ym + ((size_t)b * TT + row) * DD + h * HD;
#pragma unroll
                    for (int nt = 0; nt < 8; nt++) {
                        const int col = nt * 8 + 2 * c;
                        const float v0 = acc[mt][nt][2*half]   + Facc[rl * FAS + col]     + yr[col];
                        const float v1 = acc[mt][nt][2*half+1] + Facc[rl * FAS + col + 1] + yr[col + 1];
                        *(uint32_t*)(op + col) = packf(v0, v1);
                    }
                }
            }
        }
    }
}

// ---------------------------------------------------------------------------
extern "C" void kernel_launch(void* const* d_in, const int* in_sizes, int n_in,
                              void* d_out, int out_size)
{
    (void)in_sizes; (void)n_in; (void)out_size;
    const float* x      = (const float*)d_in[0];
    const float* w_attn = (const float*)d_in[1];
    const float* b_attn = (const float*)d_in[2];
    const float* w_k2   = (const float*)d_in[3];
    const float* b_k2   = (const float*)d_in[4];
    const float* w_proj = (const float*)d_in[5];
    const float* b_proj = (const float*)d_in[6];
    float* out = (float*)d_out;

    __half *xhp, *qkp, *ymp, *kap, *ep, *wap, *wkp, *wpp;
    float *yarp;
    cudaGetSymbolAddress((void**)&xhp,  g_xh);
    cudaGetSymbolAddress((void**)&qkp,  g_qk);
    cudaGetSymbolAddress((void**)&yarp, g_yar);
    cudaGetSymbolAddress((void**)&ymp,  g_ym);
    cudaGetSymbolAddress((void**)&kap,  g_ka);
    cudaGetSymbolAddress((void**)&ep,   g_e);
    cudaGetSymbolAddress((void**)&wap,  g_wa);
    cudaGetSymbolAddress((void**)&wkp,  g_wk);
    cudaGetSymbolAddress((void**)&wpp,  g_wp);

    cudaFuncSetAttribute(gemm_tc,     cudaFuncAttributeMaxDynamicSharedMemorySize, GEMM_SMEM);
    cudaFuncSetAttribute(flash_ar_tc, cudaFuncAttributeMaxDynamicSharedMemorySize, FLASH_SMEM);
    cudaFuncSetAttribute(flash_ma_tc, cudaFuncAttributeMaxDynamicSharedMemorySize, FLASH_SMEM);

    // R10-proven resource pattern: exactly ONE side stream + three events.
    cudaStream_t side;
    cudaStreamCreate(&side);
    cudaEvent_t evRoot, evX, evSide;
    cudaEventCreateWithFlags(&evRoot, cudaEventDisableTiming);
    cudaEventCreateWithFlags(&evX,    cudaEventDisableTiming);
    cudaEventCreateWithFlags(&evSide, cudaEventDisableTiming);

    cudaEventRecord(evRoot, 0);
    cudaStreamWaitEvent(side, evRoot, 0);

    // main: round x + w_attn -> gemm1
    round_h_kernel<<<(MM*DD/8 + 255)/256, 256>>>(x, xhp, MM*DD/8);
    round_h_kernel<<<(2*DD*DD/8 + 255)/256, 256>>>(w_attn, wap, 2*DD*DD/8);
    cudaEventRecord(evX, 0);

    // side: round w_k2 + w_proj; gemm2 -> ka (sigmoid fused)
    round_h_kernel<<<(DD*DD/8 + 255)/256, 256, 0, side>>>(w_k2, wkp, DD*DD/8);
    round_h_kernel<<<(DD*DD/8 + 255)/256, 256, 0, side>>>(w_proj, wpp, DD*DD/8);
    cudaStreamWaitEvent(side, evX, 0);
    gemm_tc<<<dim3(DD/128, MM/128), 256, GEMM_SMEM, side>>>(xhp, wkp, b_k2, 1.f, kap, 2, DD, DD);
    cudaEventRecord(evSide, side);

    // main: gemm1 -> flash_ar (writes yar + e)
    gemm_tc<<<dim3((2*DD)/128, MM/128), 256, GEMM_SMEM>>>(xhp, wap, b_attn, 1.f, qkp, 1, 2*DD, DD);
    flash_ar_tc<<<dim3(TT/128, BB*HH), 256, FLASH_SMEM>>>(qkp, xhp, x, yarp, ep);

    // join, then flash_ma -> gemm3
    cudaStreamWaitEvent(0, evSide, 0);
    flash_ma_tc<<<dim3(TT/128, BB*HH), 256, FLASH_SMEM>>>(qkp, kap, ep, yarp, ymp);
    gemm_tc<<<dim3(DD/128, MM/128), 256, GEMM_SMEM>>>(ymp, wpp, b_proj, 2.f, out, 0, DD, DD);
}

// round 16
// speedup vs baseline: 1.0543x; 1.0543x over previous
#include <cuda_runtime.h>
#include <cuda_fp16.h>
#include <math.h>
#include <stdint.h>

#define BB 2
#define TT 2048
#define DD 1024
#define HH 16
#define HD 64
#define MM (BB*TT)

// Scratch (device globals: no allocations allowed)
__device__ __half g_xh [(size_t)MM * DD];      // rounded x (half)
__device__ __half g_qk [(size_t)MM * 2 * DD];  // q|k projections (half)
__device__ float  g_yar[(size_t)MM * DD];      // y_ar fp32
__device__ __half g_ym [(size_t)MM * DD];      // rnd(y_ar + y_ma) half
__device__ __half g_ka [(size_t)MM * DD];      // sigmoid(k2*.0025) half (row T-1 don't-care)
__device__ __half g_e  [(size_t)MM * DD];      // x[t+1]-yar[t] half, row T-1 = 0
__device__ __half g_wa [(size_t)2*DD*DD];      // w_attn half
__device__ __half g_wk [(size_t)DD*DD];        // w_k2 half
__device__ __half g_wp [(size_t)DD*DD];        // w_proj half

// ---------------------------------------------------------------------------
__device__ __forceinline__ uint32_t h2u(__half2 h) { return *(uint32_t*)&h; }
__device__ __forceinline__ uint32_t packf(float a, float b) {
    __half2 h = __floats2half2_rn(a, b); return h2u(h);
}
__device__ __forceinline__ void mma16(float* d, const uint32_t* a, const uint32_t* b) {
    asm("mma.sync.aligned.m16n8k16.row.col.f32.f16.f16.f32 "
        "{%0,%1,%2,%3},{%4,%5,%6,%7},{%8,%9},{%0,%1,%2,%3};"
        : "+f"(d[0]), "+f"(d[1]), "+f"(d[2]), "+f"(d[3])
        : "r"(a[0]), "r"(a[1]), "r"(a[2]), "r"(a[3]), "r"(b[0]), "r"(b[1]));
}
__device__ __forceinline__ void ldsm4(uint32_t* r, uint32_t addr) {
    asm volatile("ldmatrix.sync.aligned.m8n8.x4.shared.b16 {%0,%1,%2,%3}, [%4];"
        : "=r"(r[0]), "=r"(r[1]), "=r"(r[2]), "=r"(r[3]) : "r"(addr));
}
__device__ __forceinline__ void ldsm4t(uint32_t* r, uint32_t addr) {
    asm volatile("ldmatrix.sync.aligned.m8n8.x4.trans.shared.b16 {%0,%1,%2,%3}, [%4];"
        : "=r"(r[0]), "=r"(r[1]), "=r"(r[2]), "=r"(r[3]) : "r"(addr));
}
__device__ __forceinline__ void cpa16(void* dst, const void* src) {
    uint32_t d = (uint32_t)__cvta_generic_to_shared(dst);
    asm volatile("cp.async.cg.shared.global [%0], [%1], 16;" :: "r"(d), "l"(src));
}
__device__ __forceinline__ uint32_t ex2h2(uint32_t t) {
    uint32_t r;
    asm("ex2.approx.f16x2 %0, %1;" : "=r"(r) : "r"(t));
    return r;
}
#define CP_COMMIT asm volatile("cp.async.commit_group;" ::: "memory")
#define CP_WAIT1  asm volatile("cp.async.wait_group 1;" ::: "memory")
#define CP_WAIT0  asm volatile("cp.async.wait_group 0;" ::: "memory")

// ---------------------------------------------------------------------------
// Fused elementwise f32 -> f16 rounding over TWO tensors in one launch.
// Each thread handles 8 floats; blocks [0, nb1) cover tensor 1, rest tensor 2.
// ---------------------------------------------------------------------------
__global__ void __launch_bounds__(256) round2_h_kernel(
    const float* __restrict__ in1, __half* __restrict__ out1, int n1_8,
    const float* __restrict__ in2, __half* __restrict__ out2, int n2_8)
{
    int i = blockIdx.x * 256 + threadIdx.x;
    const float* in; __half* out; int n;
    if (i < n1_8) { in = in1; out = out1; n = n1_8; }
    else          { in = in2; out = out2; n = n2_8; i -= n1_8; }
    if (i < n) {
        float4 a = ((const float4*)in)[2*i], b = ((const float4*)in)[2*i+1];
        uint4 r = make_uint4(packf(a.x, a.y), packf(a.z, a.w),
                             packf(b.x, b.y), packf(b.z, b.w));
        ((uint4*)out)[i] = r;
    }
}

// ---------------------------------------------------------------------------
// GEMM (R12-proven): C = A*W^T + bscale*bias. 128x128 tile, 8 warps (2m x 4n),
// Kc=32, 3-stage cp.async, one sync per iter.
// out_mode: 0 = f32, 1 = f16, 2 = f16 sigmoid(v*0.0025)  (ka path)
// ---------------------------------------------------------------------------
#define GST 40
#define GSTAGE (2 * 128 * GST)                 // halves per stage (A+W)
#define GEMM_SMEM (3 * GSTAGE * 2)             // 61440 B
__global__ void __launch_bounds__(256, 2) gemm_tc(
    const __half* __restrict__ A, const __half* __restrict__ W,
    const float* __restrict__ bias, float bscale,
    void* __restrict__ Cout, int out_mode, int N, int K)
{
    extern __shared__ __half gsm[];
    const int tid = threadIdx.x;
    const int wid = tid >> 5, lane = tid & 31;
    const int g = lane >> 2, c = lane & 3;
    const int r8 = lane & 7, sel = lane >> 3;
    const int m0 = blockIdx.y << 7, n0 = blockIdx.x << 7;
    const int wm = (wid >> 2) << 6;
    const int wn = (wid & 3) << 5;

    const int nit = K >> 5;
    float acc[4][4][4] = {};

    auto issue = [&](int it, int st) {
        __half* As = gsm + st * GSTAGE;
        __half* Ws = As + 128 * GST;
        const int k0 = it << 5;
#pragma unroll
        for (int l = 0; l < 4; l++) {
            int id = tid + l * 256;
            int arr = id >> 9, idr = id & 511;
            int r = idr >> 2, ch = (idr & 3) << 3;
            if (!arr) cpa16(&As[r * GST + ch], A + (size_t)(m0 + r) * K + k0 + ch);
            else      cpa16(&Ws[r * GST + ch], W + (size_t)(n0 + r) * K + k0 + ch);
        }
        CP_COMMIT;
    };

    issue(0, 0);
    issue(1, 1);
    for (int it = 0; it < nit; it++) {
        const int cur = it % 3;
        if (it + 1 < nit) { CP_WAIT1; } else { CP_WAIT0; }
        __syncthreads();
        if (it + 2 < nit) issue(it + 2, (it + 2) % 3);
        const __half* As = gsm + cur * GSTAGE;
        const __half* Ws = As + 128 * GST;
#pragma unroll
        for (int kk = 0; kk < 32; kk += 16) {
            uint32_t a[4][4], b[4][2];
#pragma unroll
            for (int mt = 0; mt < 4; mt++) {
                const int row = wm + mt * 16 + r8 + ((sel & 1) << 3);
                const int col = kk + ((sel >> 1) << 3);
                ldsm4(a[mt], (uint32_t)__cvta_generic_to_shared(&As[row * GST + col]));
            }
#pragma unroll
            for (int np = 0; np < 2; np++) {
                const int row = wn + ((2 * np + (sel >> 1)) << 3) + r8;
                const int col = kk + ((sel & 1) << 3);
                uint32_t t4[4];
                ldsm4(t4, (uint32_t)__cvta_generic_to_shared(&Ws[row * GST + col]));
                b[2*np][0] = t4[0]; b[2*np][1] = t4[1];
                b[2*np+1][0] = t4[2]; b[2*np+1][1] = t4[3];
            }
#pragma unroll
            for (int mt = 0; mt < 4; mt++)
#pragma unroll
                for (int nt = 0; nt < 4; nt++)
                    mma16(acc[mt][nt], a[mt], b[nt]);
        }
    }
#pragma unroll
    for (int mt = 0; mt < 4; mt++) {
#pragma unroll
        for (int nt = 0; nt < 4; nt++) {
            const int col = n0 + wn + nt * 8 + 2 * c;
            const float b0 = bscale * bias[col], b1 = bscale * bias[col + 1];
            const int row = m0 + wm + mt * 16 + g;
            float v0 = acc[mt][nt][0] + b0, v1 = acc[mt][nt][1] + b1;
            float v2 = acc[mt][nt][2] + b0, v3 = acc[mt][nt][3] + b1;
            if (out_mode == 0) {
                float* Cf = (float*)Cout;
                *(float2*)(Cf + (size_t)row * N + col) = make_float2(v0, v1);
                *(float2*)(Cf + (size_t)(row + 8) * N + col) = make_float2(v2, v3);
            } else {
                if (out_mode == 2) {
                    v0 = 1.f / (1.f + __expf(-v0 * 0.0025f));
                    v1 = 1.f / (1.f + __expf(-v1 * 0.0025f));
                    v2 = 1.f / (1.f + __expf(-v2 * 0.0025f));
                    v3 = 1.f / (1.f + __expf(-v3 * 0.0025f));
                }
                __half* Ch = (__half*)Cout;
                *(uint32_t*)(Ch + (size_t)row * N + col) = packf(v0, v1);
                *(uint32_t*)(Ch + (size_t)(row + 8) * N + col) = packf(v2, v3);
            }
        }
    }
}

// ---------------------------------------------------------------------------
// Flash kernels (R12-proven layout): Q 128 x KV 64, 8 warps x 16 q-rows,
// fp16 mma + ldmatrix, 3-stage cp.async, occupancy 2.
// flash_ar: static-shift softmax p = exp(s-3) via ex2.f16x2 fused into the
// P pack; li via ones-mma. Epilogue fuses e = h(x[t+1]-yar[t]).
// ---------------------------------------------------------------------------
#define QST 72
#define KST 72
#define OFF_K (128*QST)              // halves
#define FST   (2*64*KST)             // K+V halves per stage
#define FLASH_SMEM ((128*QST + 3*FST) * 2)   // 73728 B

__global__ void __launch_bounds__(256, 2) flash_ar_tc(
    const __half* __restrict__ qk, const __half* __restrict__ xh,
    const float* __restrict__ xf,
    float* __restrict__ yar, __half* __restrict__ eout)
{
    extern __shared__ __half fsm[];
    __half* Qs = fsm;

    const int qt = (gridDim.x - 1) - blockIdx.x;   // heavy tiles first
    const int b = blockIdx.y >> 4, h = blockIdx.y & 15;
    const int tid = threadIdx.x, wid = tid >> 5, lane = tid & 31;
    const int g = lane >> 2, c = lane & 3;
    const int r8 = lane & 7, sel = lane >> 3;
    const int q0 = qt << 7;
    const int qrow = wid << 4;

    const __half* qbase = qk + (size_t)b * TT * (2 * DD) + h * HD;
    const __half* kbase = qbase + DD;
    const __half* vbase = xh + (size_t)b * TT * DD + h * HD;

    auto issue = [&](int kt, int st) {
        __half* Ksm = fsm + OFF_K + st * FST;
        __half* Vsm = Ksm + 64 * KST;
        const int k0 = kt << 6;
#pragma unroll
        for (int l = 0; l < 4; l++) {
            int id = tid + l * 256;
            int arr = id >> 9, idr = id & 511;
            int r = idr >> 3, ch = (idr & 7) << 3;
            if (!arr) cpa16(&Ksm[r * KST + ch], kbase + (size_t)(k0 + r) * (2 * DD) + ch);
            else      cpa16(&Vsm[r * KST + ch], vbase + (size_t)(k0 + r) * DD + ch);
        }
        CP_COMMIT;
    };

    const int nkt = 2 * qt + 2;
    {
        const __half2 sc = __float2half2_rn(0.125f);
#pragma unroll
        for (int l = 0; l < 4; l++) {
            int id = tid + l * 256;
            int r = id >> 3, ch = (id & 7) << 3;
            uint4 v = *(const uint4*)(qbase + (size_t)(q0 + r) * (2 * DD) + ch);
            __half2* p = (__half2*)&v;
            p[0] = __hmul2(p[0], sc); p[1] = __hmul2(p[1], sc);
            p[2] = __hmul2(p[2], sc); p[3] = __hmul2(p[3], sc);
            *(uint4*)&Qs[r * QST + ch] = v;
        }
    }
    issue(0, 0);
    if (nkt > 1) issue(1, 1);
    __syncthreads();

    uint32_t aq[4][4];
#pragma unroll
    for (int ks = 0; ks < 4; ks++) {
        const int row = qrow + r8 + ((sel & 1) << 3);
        const int col = ks * 16 + ((sel >> 1) << 3);
        ldsm4(aq[ks], (uint32_t)__cvta_generic_to_shared(&Qs[row * QST + col]));
    }

    const uint32_t ones[2] = {0x3C003C00u, 0x3C003C00u};
    float accli[4] = {};
    float acc[8][4] = {};

    for (int kt = 0; kt < nkt; kt++) {
        const int cur = kt % 3;
        const int k0 = kt << 6;
        if (kt + 1 < nkt) { CP_WAIT1; } else { CP_WAIT0; }
        __syncthreads();
        if (kt + 2 < nkt) issue(kt + 2, (kt + 2) % 3);
        const __half* Ksm = fsm + OFF_K + cur * FST;
        const __half* Vsm = Ksm + 64 * KST;

        float s[8][4] = {};
#pragma unroll
        for (int ks = 0; ks < 4; ks++) {
            uint32_t bk[8][2];
#pragma unroll
            for (int np = 0; np < 4; np++) {
                const int row = ((2 * np + (sel >> 1)) << 3) + r8;
                const int col = ks * 16 + ((sel & 1) << 3);
                uint32_t t4[4];
                ldsm4(t4, (uint32_t)__cvta_generic_to_shared(&Ksm[row * KST + col]));
                bk[2*np][0] = t4[0]; bk[2*np][1] = t4[1];
                bk[2*np+1][0] = t4[2]; bk[2*np+1][1] = t4[3];
            }
#pragma unroll
            for (int nt = 0; nt < 8; nt++)
                mma16(s[nt], aq[ks], bk[nt]);
        }
        if (kt >= 2 * qt) {
            const int rr0 = q0 + qrow + g, rr1 = rr0 + 8;
#pragma unroll
            for (int nt = 0; nt < 8; nt++) {
                const int col = k0 + nt * 8 + 2 * c;
                if (col     > rr0) s[nt][0] = -INFINITY;
                if (col + 1 > rr0) s[nt][1] = -INFINITY;
                if (col     > rr1) s[nt][2] = -INFINITY;
                if (col + 1 > rr1) s[nt][3] = -INFINITY;
            }
        }
        const float L2E = 1.44269504f, C3 = 4.32808512f;
        uint32_t ap[4][4];
#pragma unroll
        for (int ks = 0; ks < 4; ks++) {
#pragma unroll
            for (int r = 0; r < 4; r++) {
                const int nt = 2 * ks + (r >> 1);
                const int j0 = (r & 1) << 1;
                ap[ks][r] = ex2h2(packf(fmaf(s[nt][j0],     L2E, -C3),
                                        fmaf(s[nt][j0 + 1], L2E, -C3)));
            }
        }
#pragma unroll
        for (int ks = 0; ks < 4; ks++) {
            uint32_t bv[8][2];
#pragma unroll
            for (int np = 0; np < 4; np++) {
                const int row = ks * 16 + ((sel & 1) << 3) + r8;
                const int col = ((2 * np + (sel >> 1)) << 3);
                uint32_t t4[4];
                ldsm4t(t4, (uint32_t)__cvta_generic_to_shared(&Vsm[row * KST + col]));
                bv[2*np][0] = t4[0]; bv[2*np][1] = t4[1];
                bv[2*np+1][0] = t4[2]; bv[2*np+1][1] = t4[3];
            }
#pragma unroll
            for (int nt = 0; nt < 8; nt++)
                mma16(acc[nt], ap[ks], bv[nt]);
            mma16(accli, ap[ks], ones);
        }
    }
    const float inv[2] = {1.f / accli[0], 1.f / accli[2]};
    const int row0 = q0 + qrow + g;
#pragma unroll
    for (int pass = 0; pass < 2; pass++) {
        const int t = row0 + pass * 8;
        float* opy = yar + ((size_t)b * TT + t) * DD + h * HD;
        __half* ope = eout + ((size_t)b * TT + t) * DD + h * HD;
        const float* xr = xf + ((size_t)b * TT + t + 1) * DD + h * HD;
        const bool has_e = (t < TT - 1);
#pragma unroll
        for (int nt = 0; nt < 8; nt++) {
            const int col = nt * 8 + 2 * c;
            const float y0 = acc[nt][2 * pass] * inv[pass];
            const float y1 = acc[nt][2 * pass + 1] * inv[pass];
            *(float2*)(opy + col) = make_float2(y0, y1);
            if (has_e) {
                float2 xv = *(const float2*)(xr + col);
                *(uint32_t*)(ope + col) = packf(xv.x - y0, xv.y - y1);
            } else {
                *(uint32_t*)(ope + col) = 0u;
            }
        }
    }
}

__global__ void __launch_bounds__(256, 2) flash_ma_tc(
    const __half* __restrict__ qk, const __half* __restrict__ ka,
    const __half* __restrict__ ev, const float* __restrict__ yar,
    __half* __restrict__ ym)
{
    extern __shared__ __half fsm[];
    __half* Qs = fsm;

    const int qt = (gridDim.x - 1) - blockIdx.x;
    const int b = blockIdx.y >> 4, h = blockIdx.y & 15;
    const int tid = threadIdx.x, wid = tid >> 5, lane = tid & 31;
    const int g = lane >> 2, c = lane & 3;
    const int r8 = lane & 7, sel = lane >> 3;
    const int q0 = qt << 7;
    const int qrow = wid << 4;
    const int Tm = TT - 1;

    const __half* qbase = qk + (size_t)b * TT * (2 * DD) + h * HD;
    const __half* kbase = ka + (size_t)b * TT * DD + h * HD;
    const __half* vbase = ev + (size_t)b * TT * DD + h * HD;

    if (qt == 0 && tid < HD)
        ym[(size_t)b * TT * DD + h * HD + tid] =
            __float2half(yar[(size_t)b * TT * DD + h * HD + tid]);

    auto issue = [&](int kt, int st) {
        __half* Ksm = fsm + OFF_K + st * FST;
        __half* Vsm = Ksm + 64 * KST;
        const int k0 = kt << 6;
#pragma unroll
        for (int l = 0; l < 4; l++) {
            int id = tid + l * 256;
            int arr = id >> 9, idr = id & 511;
            int r = idr >> 3, ch = (idr & 7) << 3;
            if (!arr) cpa16(&Ksm[r * KST + ch], kbase + (size_t)(k0 + r) * DD + ch);
            else      cpa16(&Vsm[r * KST + ch], vbase + (size_t)(k0 + r) * DD + ch);
        }
        CP_COMMIT;
    };

    const int nkt = 2 * qt + 2;
#pragma unroll
    for (int l = 0; l < 4; l++) {
        int id = tid + l * 256;
        int r = id >> 3, ch = (id & 7) << 3;
        int t = q0 + r;
        uint4 o = make_uint4(0u, 0u, 0u, 0u);
        if (t < Tm) {
            uint4 v = *(const uint4*)(qbase + (size_t)(t + 1) * (2 * DD) + ch);
            const __half2* p = (const __half2*)&v;
            uint32_t* q = (uint32_t*)&o;
#pragma unroll
            for (int j = 0; j < 4; j++) {
                float2 f = __half22float2(p[j]);
                f.x *= 0.125f; f.y *= 0.125f;
                q[j] = packf(fminf(f.x, 0.02f * f.x), fminf(f.y, 0.02f * f.y));
            }
        }
        *(uint4*)&Qs[r * QST + ch] = o;
    }
    issue(0, 0);
    if (nkt > 1) issue(1, 1);
    __syncthreads();

    uint32_t aq[4][4];
#pragma unroll
    for (int ks = 0; ks < 4; ks++) {
        const int row = qrow + r8 + ((sel & 1) << 3);
        const int col = ks * 16 + ((sel >> 1) << 3);
        ldsm4(aq[ks], (uint32_t)__cvta_generic_to_shared(&Qs[row * QST + col]));
    }

    float acc[8][4] = {};
    for (int kt = 0; kt < nkt; kt++) {
        const int cur = kt % 3;
        const int k0 = kt << 6;
        if (kt + 1 < nkt) { CP_WAIT1; } else { CP_WAIT0; }
        __syncthreads();
        if (kt + 2 < nkt) issue(kt + 2, (kt + 2) % 3);
        const __half* Ksm = fsm + OFF_K + cur * FST;
        const __half* Vsm = Ksm + 64 * KST;

        float s[8][4] = {};
#pragma unroll
        for (int ks = 0; ks < 4; ks++) {
            uint32_t bk[8][2];
#pragma unroll
            for (int np = 0; np < 4; np++) {
                const int row = ((2 * np + (sel >> 1)) << 3) + r8;
                const int col = ks * 16 + ((sel & 1) << 3);
                uint32_t t4[4];
                ldsm4(t4, (uint32_t)__cvta_generic_to_shared(&Ksm[row * KST + col]));
                bk[2*np][0] = t4[0]; bk[2*np][1] = t4[1];
                bk[2*np+1][0] = t4[2]; bk[2*np+1][1] = t4[3];
            }
#pragma unroll
            for (int nt = 0; nt < 8; nt++)
                mma16(s[nt], aq[ks], bk[nt]);
        }
        if (kt >= 2 * qt) {
            const int rr0 = q0 + qrow + g, rr1 = rr0 + 8;
#pragma unroll
            for (int nt = 0; nt < 8; nt++) {
                const int col = k0 + nt * 8 + 2 * c;
                if (col     > rr0) s[nt][0] = 0.f;
                if (col + 1 > rr0) s[nt][1] = 0.f;
                if (col     > rr1) s[nt][2] = 0.f;
                if (col + 1 > rr1) s[nt][3] = 0.f;
            }
        }
        uint32_t ap[4][4];
#pragma unroll
        for (int ks = 0; ks < 4; ks++) {
            ap[ks][0] = packf(s[2*ks][0],   s[2*ks][1]);
            ap[ks][1] = packf(s[2*ks][2],   s[2*ks][3]);
            ap[ks][2] = packf(s[2*ks+1][0], s[2*ks+1][1]);
            ap[ks][3] = packf(s[2*ks+1][2], s[2*ks+1][3]);
        }
#pragma unroll
        for (int ks = 0; ks < 4; ks++) {
            uint32_t bv[8][2];
#pragma unroll
            for (int np = 0; np < 4; np++) {
                const int row = ks * 16 + ((sel & 1) << 3) + r8;
                const int col = ((2 * np + (sel >> 1)) << 3);
                uint32_t t4[4];
                ldsm4t(t4, (uint32_t)__cvta_generic_to_shared(&Vsm[row * KST + col]));
                bv[2*np][0] = t4[0]; bv[2*np][1] = t4[1];
                bv[2*np+1][0] = t4[2]; bv[2*np+1][1] = t4[3];
            }
#pragma unroll
            for (int nt = 0; nt < 8; nt++)
                mma16(acc[nt], ap[ks], bv[nt]);
        }
    }
    const int t0r = q0 + qrow + g;
    if (t0r < Tm) {
        const int row = t0r + 1;
        const float* yr = yar + ((size_t)b * TT + row) * DD + h * HD;
        __half* op = ym + ((size_t)b * TT + row) * DD + h * HD;
#pragma unroll
        for (int nt = 0; nt < 8; nt++) {
            const int col = nt * 8 + 2 * c;
            *(uint32_t*)(op + col) = packf(acc[nt][0] + yr[col],
                                           acc[nt][1] + yr[col + 1]);
        }
    }
    if (t0r + 8 < Tm) {
        const int row = t0r + 9;
        const float* yr = yar + ((size_t)b * TT + row) * DD + h * HD;
        __half* op = ym + ((size_t)b * TT + row) * DD + h * HD;
#pragma unroll
        for (int nt = 0; nt < 8; nt++) {
            const int col = nt * 8 + 2 * c;
            *(uint32_t*)(op + col) = packf(acc[nt][2] + yr[col],
                                           acc[nt][3] + yr[col + 1]);
        }
    }
}

// ---------------------------------------------------------------------------
extern "C" void kernel_launch(void* const* d_in, const int* in_sizes, int n_in,
                              void* d_out, int out_size)
{
    (void)in_sizes; (void)n_in; (void)out_size;
    const float* x      = (const float*)d_in[0];
    const float* w_attn = (const float*)d_in[1];
    const float* b_attn = (const float*)d_in[2];
    const float* w_k2   = (const float*)d_in[3];
    const float* b_k2   = (const float*)d_in[4];
    const float* w_proj = (const float*)d_in[5];
    const float* b_proj = (const float*)d_in[6];
    float* out = (float*)d_out;

    __half *xhp, *qkp, *ymp, *kap, *ep, *wap, *wkp, *wpp;
    float *yarp;
    cudaGetSymbolAddress((void**)&xhp,  g_xh);
    cudaGetSymbolAddress((void**)&qkp,  g_qk);
    cudaGetSymbolAddress((void**)&yarp, g_yar);
    cudaGetSymbolAddress((void**)&ymp,  g_ym);
    cudaGetSymbolAddress((void**)&kap,  g_ka);
    cudaGetSymbolAddress((void**)&ep,   g_e);
    cudaGetSymbolAddress((void**)&wap,  g_wa);
    cudaGetSymbolAddress((void**)&wkp,  g_wk);
    cudaGetSymbolAddress((void**)&wpp,  g_wp);

    cudaFuncSetAttribute(gemm_tc,     cudaFuncAttributeMaxDynamicSharedMemorySize, GEMM_SMEM);
    cudaFuncSetAttribute(flash_ar_tc, cudaFuncAttributeMaxDynamicSharedMemorySize, FLASH_SMEM);
    cudaFuncSetAttribute(flash_ma_tc, cudaFuncAttributeMaxDynamicSharedMemorySize, FLASH_SMEM);

    // R10-proven resource pattern: exactly ONE side stream + three events.
    cudaStream_t side;
    cudaStreamCreate(&side);
    cudaEvent_t evRoot, evX, evSide;
    cudaEventCreateWithFlags(&evRoot, cudaEventDisableTiming);
    cudaEventCreateWithFlags(&evX,    cudaEventDisableTiming);
    cudaEventCreateWithFlags(&evSide, cudaEventDisableTiming);

    cudaEventRecord(evRoot, 0);
    cudaStreamWaitEvent(side, evRoot, 0);

    // main: fused round of x + w_attn (one launch) -> gemm1
    {
        const int n1 = MM*DD/8, n2 = 2*DD*DD/8;
        round2_h_kernel<<<(n1 + n2 + 255)/256, 256>>>(x, xhp, n1, w_attn, wap, n2);
    }
    cudaEventRecord(evX, 0);

    // side: fused round of w_k2 + w_proj (one launch); gemm2 -> ka (sigmoid fused)
    {
        const int n1 = DD*DD/8, n2 = DD*DD/8;
        round2_h_kernel<<<(n1 + n2 + 255)/256, 256, 0, side>>>(w_k2, wkp, n1, w_proj, wpp, n2);
    }
    cudaStreamWaitEvent(side, evX, 0);
    gemm_tc<<<dim3(DD/128, MM/128), 256, GEMM_SMEM, side>>>(xhp, wkp, b_k2, 1.f, kap, 2, DD, DD);
    cudaEventRecord(evSide, side);

    // main: gemm1 -> flash_ar (writes yar + e)
    gemm_tc<<<dim3((2*DD)/128, MM/128), 256, GEMM_SMEM>>>(xhp, wap, b_attn, 1.f, qkp, 1, 2*DD, DD);
    flash_ar_tc<<<dim3(TT/128, BB*HH), 256, FLASH_SMEM>>>(qkp, xhp, x, yarp, ep);

    // join, then flash_ma -> gemm3
    cudaStreamWaitEvent(0, evSide, 0);
    flash_ma_tc<<<dim3(TT/128, BB*HH), 256, FLASH_SMEM>>>(qkp, kap, ep, yarp, ymp);
    gemm_tc<<<dim3(DD/128, MM/128), 256, GEMM_SMEM>>>(ymp, wpp, b_proj, 2.f, out, 0, DD, DD);
}